// round 1
// baseline (speedup 1.0000x reference)
#include <cuda_runtime.h>
#include <cstdint>

// ---------------------------------------------------------------------------
// DSS kernel: out[l,h] = Re( sum_n Wk[h,n] * exp(dtLambda[h,n] * l) )
// Fixed shapes: H=1024, N=64, L=2048.  Fastpath uses a stride-32 complex
// geometric recurrence with packed f32x2 math; generic fallback otherwise.
// ---------------------------------------------------------------------------

#define EPS2 1e-14f   // EPS^2, EPS = 1e-7

// ---- scratch (device globals; no allocation allowed) ----
#define MAXHN  65536            // H*N max
#define MAXS0  (MAXHN * 32)     // s0 table entries (per p=0..31)
#define MAXOUT (2048 * 1024)    // L*H max

__device__ float g_a[MAXHN];      // Re(dtLambda)
__device__ float g_b[MAXHN];      // Im(dtLambda)
__device__ float g_wkre[MAXHN];
__device__ float g_wkim[MAXHN];
__device__ float g_mre[MAXHN];    // Re(exp(32*dtLambda))
__device__ float g_mim[MAXHN];    // Im(exp(32*dtLambda))
__device__ float g_s0re[MAXS0];   // pair-packed: [(h*N/2+np)*32 + p]*2 + parity
__device__ float g_s0im[MAXS0];
__device__ float g_outT[MAXOUT];  // transposed output [h][l]

// ---- packed f32x2 helpers ----
typedef unsigned long long u64;
#define PK(d, lo, hi)   asm("mov.b64 %0, {%1, %2};" : "=l"(d) : "f"(lo), "f"(hi))
#define UPK(lo, hi, v)  asm("mov.b64 {%0, %1}, %2;" : "=f"(lo), "=f"(hi) : "l"(v))
#define MUL2(d, a, b)   asm("mul.rn.f32x2 %0, %1, %2;" : "=l"(d) : "l"(a), "l"(b))
#define ADD2(d, a, b)   asm("add.rn.f32x2 %0, %1, %2;" : "=l"(d) : "l"(a), "l"(b))
#define FMA2(d, a, b, c) asm("fma.rn.f32x2 %0, %1, %2, %3;" : "=l"(d) : "l"(a), "l"(b), "l"(c))

// ---------------------------------------------------------------------------
// Kernel 1: per (h,n) constants.
// ---------------------------------------------------------------------------
__global__ void k_prep(const float* __restrict__ log_dt,
                       const float* __restrict__ llnr,
                       const float* __restrict__ lim,
                       const float* __restrict__ W,
                       int H, int N)
{
    int idx = blockIdx.x * blockDim.x + threadIdx.x;
    if (idx >= H * N) return;
    int h = idx / N, n = idx - h * N;

    float lr  = -expf(llnr[n]);
    float li  = lim[n];
    float dtr = expf(log_dt[2 * h + 0]);
    float dti = expf(log_dt[2 * h + 1]);
    float a = dtr * lr;          // Re(dtLambda)  (< 0)
    float b = dti * li;          // Im(dtLambda)

    // reciprocal_clamped(Lam) = conj(Lam) / max(|Lam|^2, eps^2)
    float ns = fmaxf(lr * lr + li * li, EPS2);
    float rr =  lr / ns;
    float ri = -li / ns;

    // exp(dtLambda) - 1
    float ea = expf(a), sb, cb;
    sincosf(b, &sb, &cb);
    float edr = ea * cb - 1.0f;
    float edi = ea * sb;

    float wr = W[2 * idx + 0], wi = W[2 * idx + 1];
    float tr = wr * edr - wi * edi;
    float ti = wr * edi + wi * edr;
    float wkr = tr * rr - ti * ri;
    float wki = tr * ri + ti * rr;

    g_a[idx] = a;  g_b[idx] = b;
    g_wkre[idx] = wkr;  g_wkim[idx] = wki;

    // stride-32 multiplier exp(32*dtLambda)
    float e32 = expf(32.0f * a), s32, c32;
    sincosf(32.0f * b, &s32, &c32);
    g_mre[idx] = e32 * c32;
    g_mim[idx] = e32 * s32;
}

// ---------------------------------------------------------------------------
// Kernel 2: s0[h,n,p] = Wk * exp(dtLambda * p), p = 0..31, pair-packed on n.
// ---------------------------------------------------------------------------
__global__ void k_s0(int H, int N)
{
    int idx = blockIdx.x * blockDim.x + threadIdx.x;
    if (idx >= H * N * 32) return;
    int p  = idx & 31;
    int hn = idx >> 5;

    float a = g_a[hn], b = g_b[hn];
    float wr = g_wkre[hn], wi = g_wkim[hn];

    float fp = (float)p;
    float e = expf(a * fp), s, c;
    sincosf(b * fp, &s, &c);
    float er = e * c, ei = e * s;
    float sr = wr * er - wi * ei;
    float si = wr * ei + wi * er;

    int h = hn / N, n = hn - h * N;
    int np = n >> 1, par = n & 1;
    int o = ((h * (N >> 1) + np) * 32 + p) * 2 + par;
    g_s0re[o] = sr;
    g_s0im[o] = si;
}

// ---------------------------------------------------------------------------
// Kernel 3: main recurrence. 1 block per h, 32 threads. Thread p owns
// l = p + 32j, j=0..63. Two n-streams packed per f32x2 op.
// Writes transposed scratch outT[h*L + l] (coalesced).
// ---------------------------------------------------------------------------
__global__ void __launch_bounds__(32) k_main(int N, int L)
{
    int h = blockIdx.x;
    int p = threadIdx.x;
    const int NP = N >> 1;   // n-pairs
    const int J  = 64;       // L / 32

    u64 acc[J];
#pragma unroll
    for (int j = 0; j < J; j++) acc[j] = 0ULL;

    const u64* s0re = reinterpret_cast<const u64*>(g_s0re);
    const u64* s0im = reinterpret_cast<const u64*>(g_s0im);

    for (int np = 0; np < NP; np++) {
        int base = (h * NP + np) * 32 + p;
        u64 Sre = __ldg(s0re + base);
        u64 Sim = __ldg(s0im + base);

        int nn = h * N + 2 * np;
        float mre0 = __ldg(g_mre + nn), mre1 = __ldg(g_mre + nn + 1);
        float mim0 = __ldg(g_mim + nn), mim1 = __ldg(g_mim + nn + 1);
        u64 Mre, Mim, Mimn;
        PK(Mre, mre0, mre1);
        PK(Mim, mim0, mim1);
        float nm0 = -mim0, nm1 = -mim1;
        PK(Mimn, nm0, nm1);

#pragma unroll
        for (int j = 0; j < J; j++) {
            ADD2(acc[j], acc[j], Sre);
            u64 t, u;
            MUL2(t, Sre, Mre);  FMA2(t, Sim, Mimn, t);   // new Re
            MUL2(u, Sre, Mim);  FMA2(u, Sim, Mre,  u);   // new Im
            Sre = t;  Sim = u;
        }
    }

#pragma unroll
    for (int j = 0; j < J; j++) {
        float lo, hi;
        UPK(lo, hi, acc[j]);
        g_outT[h * L + p + 32 * j] = lo + hi;
    }
}

// ---------------------------------------------------------------------------
// Kernel 4: transpose outT[h][l] -> out[l][h]
// ---------------------------------------------------------------------------
__global__ void k_transpose(float* __restrict__ out, int H, int L)
{
    __shared__ float tile[32][33];
    int l0 = blockIdx.x * 32;
    int h0 = blockIdx.y * 32;
    int tx = threadIdx.x, ty = threadIdx.y;

#pragma unroll
    for (int i = ty; i < 32; i += 8)
        tile[i][tx] = g_outT[(h0 + i) * L + l0 + tx];
    __syncthreads();
#pragma unroll
    for (int i = ty; i < 32; i += 8)
        out[(l0 + i) * H + h0 + tx] = tile[tx][i];
}

// ---------------------------------------------------------------------------
// Generic fallback (correct for any shape; slow).
// ---------------------------------------------------------------------------
__global__ void k_generic(const float* __restrict__ log_dt,
                          const float* __restrict__ llnr,
                          const float* __restrict__ lim,
                          const float* __restrict__ W,
                          float* __restrict__ out,
                          int H, int N, int L)
{
    int idx = blockIdx.x * blockDim.x + threadIdx.x;
    if (idx >= L * H) return;
    int l = idx / H, h = idx - l * H;
    float dtr = expf(log_dt[2 * h + 0]);
    float dti = expf(log_dt[2 * h + 1]);
    float fl = (float)l;
    float sum = 0.0f;
    for (int n = 0; n < N; n++) {
        float lr = -expf(llnr[n]);
        float li = lim[n];
        float a = dtr * lr, b = dti * li;
        float ns = fmaxf(lr * lr + li * li, EPS2);
        float rr = lr / ns, ri = -li / ns;
        float ea = expf(a), sb, cb;
        sincosf(b, &sb, &cb);
        float edr = ea * cb - 1.0f, edi = ea * sb;
        float wr = W[(h * N + n) * 2 + 0], wi = W[(h * N + n) * 2 + 1];
        float tr = wr * edr - wi * edi, ti = wr * edi + wi * edr;
        float wkr = tr * rr - ti * ri, wki = tr * ri + ti * rr;
        float el = expf(a * fl), sl, cl;
        sincosf(b * fl, &sl, &cl);
        sum += wkr * (el * cl) - wki * (el * sl);
    }
    out[idx] = sum;
}

// ---------------------------------------------------------------------------
extern "C" void kernel_launch(void* const* d_in, const int* in_sizes, int n_in,
                              void* d_out, int out_size)
{
    const float* log_dt = (const float*)d_in[0];   // (H,2)
    const float* llnr   = (const float*)d_in[1];   // (N,)
    const float* lim    = (const float*)d_in[2];   // (N,)
    const float* W      = (const float*)d_in[3];   // (H,N,2)
    float* out = (float*)d_out;

    int H = in_sizes[0] / 2;
    int N = in_sizes[1];
    int L = out_size / H;

    bool fast = (L == 2048) && ((N & 1) == 0) && (H * N <= MAXHN) &&
                ((H & 31) == 0) && (H * L <= MAXOUT);

    if (fast) {
        int hn = H * N;
        k_prep<<<(hn + 255) / 256, 256>>>(log_dt, llnr, lim, W, H, N);
        k_s0<<<(hn * 32 + 255) / 256, 256>>>(H, N);
        k_main<<<H, 32>>>(N, L);
        dim3 tb(32, 8), tg(L / 32, H / 32);
        k_transpose<<<tg, tb>>>(out, H, L);
    } else {
        int tot = L * H;
        k_generic<<<(tot + 255) / 256, 256>>>(log_dt, llnr, lim, W, out, H, N, L);
    }
}

// round 2
// speedup vs baseline: 1.1094x; 1.1094x over previous
#include <cuda_runtime.h>
#include <cstdint>

// ---------------------------------------------------------------------------
// DSS kernel: out[l,h] = Re( sum_n Wk[h,n] * exp(dtLambda[h,n] * l) )
// Fastpath (H=1024, N=64, L=2048): real 2nd-order recurrence at stride 32,
// c_{l+32} = A*c_l - B*c_{l-32}, A=2Re(z^32), B=|z^32|^2, packed f32x2.
// ---------------------------------------------------------------------------

#define EPS2 1e-14f   // EPS^2, EPS = 1e-7

#define FH 1024
#define FN 64
#define FL 2048
#define FNP 32          // n-pairs
#define FJ  32          // recurrence steps per block (L/2/32)

// ---- scratch (device globals; no allocation allowed) ----
#define MAXHN  (FH * FN)
#define S0ELEM (FH * 2 * FNP * 32 * 2)   // 4M floats = 16MB per table

__device__ float g_a[MAXHN];        // Re(dtLambda)
__device__ float g_b[MAXHN];        // Im(dtLambda)
__device__ float g_wkre[MAXHN];
__device__ float g_wkim[MAXHN];
__device__ float g_mre[MAXHN];      // Re(exp(32*dtLambda))
__device__ float g_mim[MAXHN];      // Im(exp(32*dtLambda))
__device__ float g_qre[MAXHN];      // Re(exp(1024*dtLambda))
__device__ float g_qim[MAXHN];      // Im(exp(1024*dtLambda))
__device__ float g_An[MAXHN];       // A = 2*Re(exp(32*dtLambda))
__device__ float g_nB[MAXHN];       // -B = -exp(64*Re(dtLambda))
__device__ float g_c0f[S0ELEM];     // c at l = 1024*half + p      (pair-packed)
__device__ float g_cm1f[S0ELEM];    // c at l = 1024*half + p - 32 (pair-packed)
__device__ float g_outT[FL * FH];   // transposed output [h][l]

// ---- packed f32x2 helpers ----
typedef unsigned long long u64;
#define PK(d, lo, hi)   asm("mov.b64 %0, {%1, %2};" : "=l"(d) : "f"(lo), "f"(hi))
#define UPK(lo, hi, v)  asm("mov.b64 {%0, %1}, %2;" : "=f"(lo), "=f"(hi) : "l"(v))
#define MUL2(d, a, b)   asm("mul.rn.f32x2 %0, %1, %2;" : "=l"(d) : "l"(a), "l"(b))
#define ADD2(d, a, b)   asm("add.rn.f32x2 %0, %1, %2;" : "=l"(d) : "l"(a), "l"(b))
#define FMA2(d, a, b, c) asm("fma.rn.f32x2 %0, %1, %2, %3;" : "=l"(d) : "l"(a), "l"(b), "l"(c))

// ---------------------------------------------------------------------------
// Kernel 1: per (h,n) constants.
// ---------------------------------------------------------------------------
__global__ void k_prep(const float* __restrict__ log_dt,
                       const float* __restrict__ llnr,
                       const float* __restrict__ lim)
{
    int idx = blockIdx.x * blockDim.x + threadIdx.x;
    if (idx >= FH * FN) return;
    int h = idx >> 6, n = idx & 63;

    float lr  = -expf(llnr[n]);
    float li  = lim[n];
    float dtr = expf(log_dt[2 * h + 0]);
    float dti = expf(log_dt[2 * h + 1]);
    float a = dtr * lr;          // Re(dtLambda)  (< 0)
    float b = dti * li;          // Im(dtLambda)

    g_a[idx] = a;  g_b[idx] = b;

    // stride-32 multiplier exp(32*dtLambda)
    float e32 = expf(32.0f * a), s32, c32;
    sincosf(32.0f * b, &s32, &c32);
    float mre = e32 * c32, mim = e32 * s32;
    g_mre[idx] = mre;
    g_mim[idx] = mim;

    // stride-1024 multiplier exp(1024*dtLambda)
    float e1k = expf(1024.0f * a), s1k, c1k;
    sincosf(1024.0f * b, &s1k, &c1k);
    g_qre[idx] = e1k * c1k;
    g_qim[idx] = e1k * s1k;

    // real recurrence coefficients: A = 2*Re(m32), -B = -|m32|^2 = -e^{64a}
    g_An[idx] = 2.0f * mre;
    g_nB[idx] = -expf(64.0f * a);
}

// ---------------------------------------------------------------------------
// Kernel 1b: Wk = Wc * (exp(dtLambda)-1) * reciprocal_clamped(Lambda)
// ---------------------------------------------------------------------------
__global__ void k_wk(const float* __restrict__ log_dt,
                     const float* __restrict__ llnr,
                     const float* __restrict__ lim,
                     const float* __restrict__ W)
{
    int idx = blockIdx.x * blockDim.x + threadIdx.x;
    if (idx >= FH * FN) return;
    int n = idx & 63;

    float lr = -expf(llnr[n]);
    float li = lim[n];
    float a = g_a[idx], b = g_b[idx];

    float ns = fmaxf(lr * lr + li * li, EPS2);
    float rr =  lr / ns;
    float ri = -li / ns;

    float ea = expf(a), sb, cb;
    sincosf(b, &sb, &cb);
    float edr = ea * cb - 1.0f;
    float edi = ea * sb;

    float wr = W[2 * idx + 0], wi = W[2 * idx + 1];
    float tr = wr * edr - wi * edi;
    float ti = wr * edi + wi * edr;
    g_wkre[idx] = tr * rr - ti * ri;
    g_wkim[idx] = tr * ri + ti * rr;
}

// ---------------------------------------------------------------------------
// Kernel 2: start values. One exp+sincos per (h,n,p); derives the 4 start
// scalars (c0, cm1 for both halves) by complex multiplies with m32 / m1024.
// ---------------------------------------------------------------------------
__global__ void k_s0()
{
    int idx = blockIdx.x * blockDim.x + threadIdx.x;
    if (idx >= FH * FN * 32) return;
    int p  = idx & 31;
    int hn = idx >> 5;
    int h = hn >> 6, n = hn & 63;
    int np = n >> 1, par = n & 1;

    float a = g_a[hn], b = g_b[hn];
    float wr = g_wkre[hn], wi = g_wkim[hn];

    float lm = (float)(p - 32);
    float e = expf(a * lm), s, cc;
    sincosf(b * lm, &s, &cc);
    float Er = e * cc, Ei = e * s;                 // exp(dtL*(p-32))

    float mr = g_mre[hn], mi = g_mim[hn];
    float qr = g_qre[hn], qi = g_qim[hn];

    float v_cm1_0 = wr * Er - wi * Ei;             // l = p-32
    float E1r = Er * mr - Ei * mi;
    float E1i = Er * mi + Ei * mr;                 // l = p
    float v_c0_0  = wr * E1r - wi * E1i;
    float E2r = Er * qr - Ei * qi;
    float E2i = Er * qi + Ei * qr;                 // l = 1024+p-32
    float v_cm1_1 = wr * E2r - wi * E2i;
    float E3r = E2r * mr - E2i * mi;
    float E3i = E2r * mi + E2i * mr;               // l = 1024+p
    float v_c0_1  = wr * E3r - wi * E3i;

    int base0 = (((h * 2 + 0) * FNP + np) * 32 + p) * 2 + par;
    int base1 = (((h * 2 + 1) * FNP + np) * 32 + p) * 2 + par;
    g_cm1f[base0] = v_cm1_0;  g_c0f[base0] = v_c0_0;
    g_cm1f[base1] = v_cm1_1;  g_c0f[base1] = v_c0_1;
}

// ---------------------------------------------------------------------------
// Kernel 3: main recurrence. Block = (h, half); 32 threads; thread p owns
// l = 1024*half + p + 32j, j=0..31. 3 packed f32x2 ops per (l, n-pair).
// ---------------------------------------------------------------------------
__global__ void __launch_bounds__(32) k_main()
{
    int blk = blockIdx.x;           // h*2 + half
    int p = threadIdx.x;
    int h = blk >> 1;

    u64 acc[FJ];
#pragma unroll
    for (int j = 0; j < FJ; j++) acc[j] = 0ULL;

    const u64* c0t  = reinterpret_cast<const u64*>(g_c0f)  + blk * (FNP * 32);
    const u64* cm1t = reinterpret_cast<const u64*>(g_cm1f) + blk * (FNP * 32);

    for (int np = 0; np < FNP; np++) {
        u64 c  = __ldg(c0t  + np * 32 + p);
        u64 cm = __ldg(cm1t + np * 32 + p);

        int nn = (h << 6) + (np << 1);
        float A0 = __ldg(g_An + nn), A1 = __ldg(g_An + nn + 1);
        float B0 = __ldg(g_nB + nn), B1 = __ldg(g_nB + nn + 1);
        u64 A, nB;
        PK(A, A0, A1);
        PK(nB, B0, B1);

#pragma unroll
        for (int j = 0; j < FJ; j++) {
            ADD2(acc[j], acc[j], c);
            u64 t;
            MUL2(t, c, A);
            FMA2(t, cm, nB, t);
            cm = c;
            c = t;
        }
    }

    int l0 = (blk & 1) << 10;
#pragma unroll
    for (int j = 0; j < FJ; j++) {
        float lo, hi;
        UPK(lo, hi, acc[j]);
        g_outT[h * FL + l0 + (j << 5) + p] = lo + hi;
    }
}

// ---------------------------------------------------------------------------
// Kernel 4: transpose outT[h][l] -> out[l][h]. 4 l-tiles per block (MLP=16).
// ---------------------------------------------------------------------------
__global__ void k_transpose(float* __restrict__ out)
{
    __shared__ float tile[4][32][33];
    int l0 = blockIdx.x * 128;
    int h0 = blockIdx.y * 32;
    int tx = threadIdx.x, ty = threadIdx.y;

#pragma unroll
    for (int k = 0; k < 4; k++)
#pragma unroll
        for (int i = ty; i < 32; i += 8)
            tile[k][i][tx] = g_outT[(h0 + i) * FL + l0 + k * 32 + tx];
    __syncthreads();
#pragma unroll
    for (int k = 0; k < 4; k++)
#pragma unroll
        for (int i = ty; i < 32; i += 8)
            out[(l0 + k * 32 + i) * FH + h0 + tx] = tile[k][tx][i];
}

// ---------------------------------------------------------------------------
// Generic fallback (correct for any shape; slow).
// ---------------------------------------------------------------------------
__global__ void k_generic(const float* __restrict__ log_dt,
                          const float* __restrict__ llnr,
                          const float* __restrict__ lim,
                          const float* __restrict__ W,
                          float* __restrict__ out,
                          int H, int N, int L)
{
    int idx = blockIdx.x * blockDim.x + threadIdx.x;
    if (idx >= L * H) return;
    int l = idx / H, h = idx - l * H;
    float dtr = expf(log_dt[2 * h + 0]);
    float dti = expf(log_dt[2 * h + 1]);
    float fl = (float)l;
    float sum = 0.0f;
    for (int n = 0; n < N; n++) {
        float lr = -expf(llnr[n]);
        float li = lim[n];
        float a = dtr * lr, b = dti * li;
        float ns = fmaxf(lr * lr + li * li, EPS2);
        float rr = lr / ns, ri = -li / ns;
        float ea = expf(a), sb, cb;
        sincosf(b, &sb, &cb);
        float edr = ea * cb - 1.0f, edi = ea * sb;
        float wr = W[(h * N + n) * 2 + 0], wi = W[(h * N + n) * 2 + 1];
        float tr = wr * edr - wi * edi, ti = wr * edi + wi * edr;
        float wkr = tr * rr - ti * ri, wki = tr * ri + ti * rr;
        float el = expf(a * fl), sl, cl;
        sincosf(b * fl, &sl, &cl);
        sum += wkr * (el * cl) - wki * (el * sl);
    }
    out[idx] = sum;
}

// ---------------------------------------------------------------------------
extern "C" void kernel_launch(void* const* d_in, const int* in_sizes, int n_in,
                              void* d_out, int out_size)
{
    const float* log_dt = (const float*)d_in[0];   // (H,2)
    const float* llnr   = (const float*)d_in[1];   // (N,)
    const float* lim    = (const float*)d_in[2];   // (N,)
    const float* W      = (const float*)d_in[3];   // (H,N,2)
    float* out = (float*)d_out;

    int H = in_sizes[0] / 2;
    int N = in_sizes[1];
    int L = out_size / H;

    if (H == FH && N == FN && L == FL) {
        int hn = FH * FN;
        k_prep<<<(hn + 255) / 256, 256>>>(log_dt, llnr, lim);
        k_wk  <<<(hn + 255) / 256, 256>>>(log_dt, llnr, lim, W);
        k_s0  <<<(hn * 32 + 255) / 256, 256>>>();
        k_main<<<FH * 2, 32>>>();
        dim3 tb(32, 8), tg(FL / 128, FH / 32);
        k_transpose<<<tg, tb>>>(out);
    } else {
        int tot = L * H;
        k_generic<<<(tot + 255) / 256, 256>>>(log_dt, llnr, lim, W, out, H, N, L);
    }
}

// round 3
// speedup vs baseline: 1.3547x; 1.2212x over previous
#include <cuda_runtime.h>
#include <cstdint>

// ---------------------------------------------------------------------------
// DSS kernel: out[l,h] = Re( sum_n Wk[h,n] * exp(dtLambda[h,n] * l) )
// Fastpath (H=1024, N=64, L=2048): real 2nd-order recurrence at stride 32,
// c_{l+32} = A*c_l - B*c_{l-32}, packed f32x2, software-pipelined loads,
// fused smem transpose (direct coalesced stores to out[l,h]).
// ---------------------------------------------------------------------------

#define EPS2 1e-14f   // EPS^2, EPS = 1e-7

#define FH 1024
#define FN 64
#define FL 2048
#define FNP 32          // n-pairs
#define FJ  32          // recurrence steps per block-half (L/2/32)
#define HT  8           // h-tile per k_main block

// ---- scratch (device globals; no allocation allowed) ----
#define MAXHN  (FH * FN)
#define S0ELEM (FH * 2 * FNP * 32 * 2)   // start tables, pair-packed

__device__ __align__(16) float g_a[MAXHN];        // Re(dtLambda)
__device__ __align__(16) float g_b[MAXHN];        // Im(dtLambda)
__device__ __align__(16) float g_wkre[MAXHN];
__device__ __align__(16) float g_wkim[MAXHN];
__device__ __align__(16) float g_mre[MAXHN];      // Re(exp(32*dtL))
__device__ __align__(16) float g_mim[MAXHN];
__device__ __align__(16) float g_qre[MAXHN];      // Re(exp(1024*dtL))
__device__ __align__(16) float g_qim[MAXHN];
__device__ __align__(16) float g_An[MAXHN];       // A  = 2*Re(exp(32*dtL))
__device__ __align__(16) float g_nB[MAXHN];       // -B = -exp(64*Re(dtL))
__device__ __align__(16) float g_c0f[S0ELEM];     // c at l = 1024*half + p
__device__ __align__(16) float g_cm1f[S0ELEM];    // c at l = 1024*half + p - 32

// ---- packed f32x2 helpers ----
typedef unsigned long long u64;
#define PK(d, lo, hi)   asm("mov.b64 %0, {%1, %2};" : "=l"(d) : "f"(lo), "f"(hi))
#define UPK(lo, hi, v)  asm("mov.b64 {%0, %1}, %2;" : "=f"(lo), "=f"(hi) : "l"(v))
#define MUL2(d, a, b)   asm("mul.rn.f32x2 %0, %1, %2;" : "=l"(d) : "l"(a), "l"(b))
#define ADD2(d, a, b)   asm("add.rn.f32x2 %0, %1, %2;" : "=l"(d) : "l"(a), "l"(b))
#define FMA2(d, a, b, c) asm("fma.rn.f32x2 %0, %1, %2, %3;" : "=l"(d) : "l"(a), "l"(b), "l"(c))

// ---------------------------------------------------------------------------
// Kernel 1: per (h,n) constants (prep + Wk fused).
// ---------------------------------------------------------------------------
__global__ void k_prep(const float* __restrict__ log_dt,
                       const float* __restrict__ llnr,
                       const float* __restrict__ lim,
                       const float* __restrict__ W)
{
    int idx = blockIdx.x * blockDim.x + threadIdx.x;
    if (idx >= FH * FN) return;
    int h = idx >> 6, n = idx & 63;

    float lr  = -expf(llnr[n]);
    float li  = lim[n];
    float dtr = expf(log_dt[2 * h + 0]);
    float dti = expf(log_dt[2 * h + 1]);
    float a = dtr * lr;          // Re(dtLambda)  (< 0)
    float b = dti * li;          // Im(dtLambda)

    g_a[idx] = a;  g_b[idx] = b;

    // stride-32 multiplier
    float e32 = expf(32.0f * a), s32, c32;
    sincosf(32.0f * b, &s32, &c32);
    float mre = e32 * c32, mim = e32 * s32;
    g_mre[idx] = mre;  g_mim[idx] = mim;

    // stride-1024 multiplier
    float e1k = expf(1024.0f * a), s1k, c1k;
    sincosf(1024.0f * b, &s1k, &c1k);
    g_qre[idx] = e1k * c1k;  g_qim[idx] = e1k * s1k;

    // real recurrence coefficients
    g_An[idx] = 2.0f * mre;
    g_nB[idx] = -expf(64.0f * a);

    // Wk = Wc * (exp(dtL)-1) * reciprocal_clamped(Lambda)
    float ns = fmaxf(lr * lr + li * li, EPS2);
    float rr =  lr / ns;
    float ri = -li / ns;
    float ea = expf(a), sb, cb;
    sincosf(b, &sb, &cb);
    float edr = ea * cb - 1.0f;
    float edi = ea * sb;
    float wr = W[2 * idx + 0], wi = W[2 * idx + 1];
    float tr = wr * edr - wi * edi;
    float ti = wr * edi + wi * edr;
    g_wkre[idx] = tr * rr - ti * ri;
    g_wkim[idx] = tr * ri + ti * rr;
}

// ---------------------------------------------------------------------------
// Kernel 2: start values. One exp+sincos per (h,n,p); derives the 4 start
// scalars (c0, cm1 for both halves) via complex multiplies with m32 / m1024.
// ---------------------------------------------------------------------------
__global__ void k_s0()
{
    int idx = blockIdx.x * blockDim.x + threadIdx.x;
    if (idx >= FH * FN * 32) return;
    int p  = idx & 31;
    int hn = idx >> 5;
    int h = hn >> 6, n = hn & 63;
    int np = n >> 1, par = n & 1;

    float a = g_a[hn], b = g_b[hn];
    float wr = g_wkre[hn], wi = g_wkim[hn];

    float lm = (float)(p - 32);
    float e = expf(a * lm), s, cc;
    sincosf(b * lm, &s, &cc);
    float Er = e * cc, Ei = e * s;                 // exp(dtL*(p-32))

    float mr = g_mre[hn], mi = g_mim[hn];
    float qr = g_qre[hn], qi = g_qim[hn];

    float v_cm1_0 = wr * Er - wi * Ei;             // l = p-32
    float E1r = Er * mr - Ei * mi;
    float E1i = Er * mi + Ei * mr;                 // l = p
    float v_c0_0  = wr * E1r - wi * E1i;
    float E2r = Er * qr - Ei * qi;
    float E2i = Er * qi + Ei * qr;                 // l = 1024+p-32
    float v_cm1_1 = wr * E2r - wi * E2i;
    float E3r = E2r * mr - E2i * mi;
    float E3i = E2r * mi + E2i * mr;               // l = 1024+p
    float v_c0_1  = wr * E3r - wi * E3i;

    int base0 = (((h * 2 + 0) * FNP + np) * 32 + p) * 2 + par;
    int base1 = (((h * 2 + 1) * FNP + np) * 32 + p) * 2 + par;
    g_cm1f[base0] = v_cm1_0;  g_c0f[base0] = v_c0_0;
    g_cm1f[base1] = v_cm1_1;  g_c0f[base1] = v_c0_1;
}

// ---------------------------------------------------------------------------
// Kernel 3: main recurrence + fused transpose.
// Block = (h-tile of 8, half): 8 warps, warp w -> h = h0+w, thread p = lane.
// Thread computes l = 1024*half + p + 32j, j=0..31, summing 32 n-pairs.
// Loads for np+1 are prefetched before the j-loop of np (latency hiding).
// Epilogue stages results through smem and stores out[l, h0:h0+8] as full
// 32B sectors.
// ---------------------------------------------------------------------------
__global__ void __launch_bounds__(HT * 32, 2) k_main()
{
    // [j][p][w(+pad)] : write conflict-free (9p mod 32 distinct), ~37KB
    __shared__ float tile[FJ][32][HT + 1];

    int blk   = blockIdx.x;          // htile*2 + half
    int half  = blk & 1;
    int htile = blk >> 1;
    int w = threadIdx.x >> 5;        // warp -> h offset
    int p = threadIdx.x & 31;        // lane -> l phase
    int h = htile * HT + w;

    u64 acc[FJ];
#pragma unroll
    for (int j = 0; j < FJ; j++) acc[j] = 0ULL;

    const u64* c0t  = reinterpret_cast<const u64*>(g_c0f)  + (size_t)(h * 2 + half) * (FNP * 32) + p;
    const u64* cm1t = reinterpret_cast<const u64*>(g_cm1f) + (size_t)(h * 2 + half) * (FNP * 32) + p;
    const u64* A2   = reinterpret_cast<const u64*>(g_An) + h * FNP;
    const u64* B2   = reinterpret_cast<const u64*>(g_nB) + h * FNP;

    // prefetch np = 0
    u64 c_n  = __ldg(c0t);
    u64 cm_n = __ldg(cm1t);
    u64 A_n  = __ldg(A2);
    u64 B_n  = __ldg(B2);

    for (int np = 0; np < FNP; np++) {
        u64 c = c_n, cm = cm_n, A = A_n, nB = B_n;
        if (np + 1 < FNP) {          // prefetch next n-pair
            c_n  = __ldg(c0t  + (np + 1) * 32);
            cm_n = __ldg(cm1t + (np + 1) * 32);
            A_n  = __ldg(A2 + np + 1);
            B_n  = __ldg(B2 + np + 1);
        }
#pragma unroll
        for (int j = 0; j < FJ; j++) {
            ADD2(acc[j], acc[j], c);
            u64 t;
            MUL2(t, c, A);
            FMA2(t, cm, nB, t);
            cm = c;
            c = t;
        }
    }

    // stage to smem: tile[j][p][w] = hsum(acc[j])
#pragma unroll
    for (int j = 0; j < FJ; j++) {
        float lo, hi;
        UPK(lo, hi, acc[j]);
        tile[j][p][w] = lo + hi;
    }
    __syncthreads();

    // coalesced store: thread t -> (p-row = t>>3, h-off = t&7)
    int pp = threadIdx.x >> 3;
    int ww = threadIdx.x & 7;
    int l0 = half << 10;
    int hb = htile * HT + ww;
    float* out = (float*)0;  // patched below via param-free global? no — passed via constant
    // (out pointer comes through a __device__ global set by a tiny kernel-free
    //  trick is not allowed; instead k_main takes it as a parameter)
    // -- replaced by parameterized version; see k_main_p below --
    (void)pp; (void)ww; (void)l0; (void)hb; (void)out;
}

// Parameterized main (the one actually launched).
__global__ void __launch_bounds__(HT * 32, 2) k_main_p(float* __restrict__ out)
{
    __shared__ float tile[FJ][32][HT + 1];

    int blk   = blockIdx.x;
    int half  = blk & 1;
    int htile = blk >> 1;
    int w = threadIdx.x >> 5;
    int p = threadIdx.x & 31;
    int h = htile * HT + w;

    u64 acc[FJ];
#pragma unroll
    for (int j = 0; j < FJ; j++) acc[j] = 0ULL;

    const u64* c0t  = reinterpret_cast<const u64*>(g_c0f)  + (size_t)(h * 2 + half) * (FNP * 32) + p;
    const u64* cm1t = reinterpret_cast<const u64*>(g_cm1f) + (size_t)(h * 2 + half) * (FNP * 32) + p;
    const u64* A2   = reinterpret_cast<const u64*>(g_An) + h * FNP;
    const u64* B2   = reinterpret_cast<const u64*>(g_nB) + h * FNP;

    u64 c_n  = __ldg(c0t);
    u64 cm_n = __ldg(cm1t);
    u64 A_n  = __ldg(A2);
    u64 B_n  = __ldg(B2);

    for (int np = 0; np < FNP; np++) {
        u64 c = c_n, cm = cm_n, A = A_n, nB = B_n;
        if (np + 1 < FNP) {
            c_n  = __ldg(c0t  + (np + 1) * 32);
            cm_n = __ldg(cm1t + (np + 1) * 32);
            A_n  = __ldg(A2 + np + 1);
            B_n  = __ldg(B2 + np + 1);
        }
#pragma unroll
        for (int j = 0; j < FJ; j++) {
            ADD2(acc[j], acc[j], c);
            u64 t;
            MUL2(t, c, A);
            FMA2(t, cm, nB, t);
            cm = c;
            c = t;
        }
    }

#pragma unroll
    for (int j = 0; j < FJ; j++) {
        float lo, hi;
        UPK(lo, hi, acc[j]);
        tile[j][p][w] = lo + hi;
    }
    __syncthreads();

    int pp = threadIdx.x >> 3;       // l phase 0..31
    int ww = threadIdx.x & 7;        // h offset 0..7
    int l0 = half << 10;
    int hb = htile * HT + ww;
#pragma unroll
    for (int k = 0; k < FJ; k++)
        out[(size_t)(l0 + (k << 5) + pp) * FH + hb] = tile[k][pp][ww];
}

// ---------------------------------------------------------------------------
// Generic fallback (correct for any shape; slow).
// ---------------------------------------------------------------------------
__global__ void k_generic(const float* __restrict__ log_dt,
                          const float* __restrict__ llnr,
                          const float* __restrict__ lim,
                          const float* __restrict__ W,
                          float* __restrict__ out,
                          int H, int N, int L)
{
    int idx = blockIdx.x * blockDim.x + threadIdx.x;
    if (idx >= L * H) return;
    int l = idx / H, h = idx - l * H;
    float dtr = expf(log_dt[2 * h + 0]);
    float dti = expf(log_dt[2 * h + 1]);
    float fl = (float)l;
    float sum = 0.0f;
    for (int n = 0; n < N; n++) {
        float lr = -expf(llnr[n]);
        float li = lim[n];
        float a = dtr * lr, b = dti * li;
        float ns = fmaxf(lr * lr + li * li, EPS2);
        float rr = lr / ns, ri = -li / ns;
        float ea = expf(a), sb, cb;
        sincosf(b, &sb, &cb);
        float edr = ea * cb - 1.0f, edi = ea * sb;
        float wr = W[(h * N + n) * 2 + 0], wi = W[(h * N + n) * 2 + 1];
        float tr = wr * edr - wi * edi, ti = wr * edi + wi * edr;
        float wkr = tr * rr - ti * ri, wki = tr * ri + ti * rr;
        float el = expf(a * fl), sl, cl;
        sincosf(b * fl, &sl, &cl);
        sum += wkr * (el * cl) - wki * (el * sl);
    }
    out[idx] = sum;
}

// ---------------------------------------------------------------------------
extern "C" void kernel_launch(void* const* d_in, const int* in_sizes, int n_in,
                              void* d_out, int out_size)
{
    const float* log_dt = (const float*)d_in[0];   // (H,2)
    const float* llnr   = (const float*)d_in[1];   // (N,)
    const float* lim    = (const float*)d_in[2];   // (N,)
    const float* W      = (const float*)d_in[3];   // (H,N,2)
    float* out = (float*)d_out;

    int H = in_sizes[0] / 2;
    int N = in_sizes[1];
    int L = out_size / H;

    if (H == FH && N == FN && L == FL) {
        int hn = FH * FN;
        k_prep<<<(hn + 255) / 256, 256>>>(log_dt, llnr, lim, W);
        k_s0  <<<(hn * 32 + 255) / 256, 256>>>();
        k_main_p<<<(FH / HT) * 2, HT * 32>>>(out);
    } else {
        int tot = L * H;
        k_generic<<<(tot + 255) / 256, 256>>>(log_dt, llnr, lim, W, out, H, N, L);
    }
}

// round 4
// speedup vs baseline: 1.5269x; 1.1271x over previous
#include <cuda_runtime.h>
#include <cstdint>

// ---------------------------------------------------------------------------
// DSS kernel: out[l,h] = Re( sum_n Wk[h,n] * exp(dtLambda[h,n] * l) )
// Fastpath (H=1024, N=64, L=2048):
//   k_prep: per-(h,n) constants (precise transcendentals), 2.6MB const tables
//   k_main: seeds computed in-kernel (fast trig + Cody-Waite reduction),
//           real 2nd-order recurrence c_{l+32}=A c_l - B c_{l-32} in packed
//           f32x2, fused smem transpose, coalesced stores to out[l,h].
// ---------------------------------------------------------------------------

#define EPS2 1e-14f   // EPS^2, EPS = 1e-7

#define FH 1024
#define FN 64
#define FL 2048
#define FNP 32          // n-pairs
#define FJ  32          // recurrence steps per block-half (L/2/32)
#define HT  8           // h-tile per k_main block

#define INV_2PI 0.15915494309189535f
#define PI2_HI  6.2831854820251465f     // float(2*pi)
#define PI2_LO  (-1.7484556000744483e-7f)

// ---- const tables: one float4 per (h, n-pair), parity-packed ----
#define NT4 (FH * FNP)
__device__ __align__(16) float g_ab4[NT4 * 4];   // a0,a1,b0,b1
__device__ __align__(16) float g_wk4[NT4 * 4];   // wkr0,wkr1,wki0,wki1
__device__ __align__(16) float g_m4 [NT4 * 4];   // mr0,mr1,mi0,mi1   (z^32)
__device__ __align__(16) float g_q4 [NT4 * 4];   // qr0,qr1,qi0,qi1   (z^1024)
__device__ __align__(16) float g_AB4[NT4 * 4];   // A0,A1,-B0,-B1

// ---- packed f32x2 helpers ----
typedef unsigned long long u64;
#define PK(d, lo, hi)   asm("mov.b64 %0, {%1, %2};" : "=l"(d) : "f"(lo), "f"(hi))
#define UPK(lo, hi, v)  asm("mov.b64 {%0, %1}, %2;" : "=f"(lo), "=f"(hi) : "l"(v))
#define MUL2(d, a, b)   asm("mul.rn.f32x2 %0, %1, %2;" : "=l"(d) : "l"(a), "l"(b))
#define ADD2(d, a, b)   asm("add.rn.f32x2 %0, %1, %2;" : "=l"(d) : "l"(a), "l"(b))
#define FMA2(d, a, b, c) asm("fma.rn.f32x2 %0, %1, %2, %3;" : "=l"(d) : "l"(a), "l"(b), "l"(c))

// ---------------------------------------------------------------------------
// Kernel 1: per (h,n) constants, precise math. One thread per (h,n).
// ---------------------------------------------------------------------------
__global__ void k_prep(const float* __restrict__ log_dt,
                       const float* __restrict__ llnr,
                       const float* __restrict__ lim,
                       const float* __restrict__ W)
{
    int idx = blockIdx.x * blockDim.x + threadIdx.x;
    if (idx >= FH * FN) return;
    int h = idx >> 6, n = idx & 63;
    int np = n >> 1, par = n & 1;
    int o = (h * FNP + np) * 4;

    float lr  = -expf(llnr[n]);
    float li  = lim[n];
    float dtr = expf(log_dt[2 * h + 0]);
    float dti = expf(log_dt[2 * h + 1]);
    float a = dtr * lr;          // Re(dtLambda)  (< 0)
    float b = dti * li;          // Im(dtLambda)

    g_ab4[o + par] = a;
    g_ab4[o + 2 + par] = b;

    // z^32 (precise)
    float e32 = expf(32.0f * a), s32, c32;
    sincosf(32.0f * b, &s32, &c32);
    float mre = e32 * c32, mim = e32 * s32;
    g_m4[o + par] = mre;
    g_m4[o + 2 + par] = mim;

    // z^1024 (precise)
    float e1k = expf(1024.0f * a), s1k, c1k;
    sincosf(1024.0f * b, &s1k, &c1k);
    g_q4[o + par] = e1k * c1k;
    g_q4[o + 2 + par] = e1k * s1k;

    // recurrence coefficients: A = 2 Re(z^32), -B = -|z^32|^2
    g_AB4[o + par] = 2.0f * mre;
    g_AB4[o + 2 + par] = -expf(64.0f * a);

    // Wk = Wc * (exp(dtL)-1) * reciprocal_clamped(Lambda)
    float ns = fmaxf(lr * lr + li * li, EPS2);
    float rr =  lr / ns;
    float ri = -li / ns;
    float ea = expf(a), sb, cb;
    sincosf(b, &sb, &cb);
    float edr = ea * cb - 1.0f;
    float edi = ea * sb;
    float wr = W[2 * idx + 0], wi = W[2 * idx + 1];
    float tr = wr * edr - wi * edi;
    float ti = wr * edi + wi * edr;
    g_wk4[o + par]     = tr * rr - ti * ri;
    g_wk4[o + 2 + par] = tr * ri + ti * rr;
}

// fast sin/cos with explicit Cody-Waite reduction to [-pi, pi]
__device__ __forceinline__ void fast_sincos(float th, float* s, float* c)
{
    float k = rintf(th * INV_2PI);
    float r = fmaf(-k, PI2_HI, th);
    r = fmaf(-k, PI2_LO, r);
    *s = __sinf(r);
    *c = __cosf(r);
}

// ---------------------------------------------------------------------------
// Kernel 2: seeds + recurrence + fused transpose.
// Block = (h-tile of 8, half). Warp w -> h = h0+w; lane p -> l-phase.
// Per n-pair: seeds from exp(dtL*(p-32)) [fast trig], optional *q rotation
// for the upper half, then 32 unrolled steps of
//   acc[j] += c;  c' = A*c - B*cm   (packed f32x2, two n per op).
// ---------------------------------------------------------------------------
__global__ void __launch_bounds__(HT * 32, 2) k_main(float* __restrict__ out)
{
    __shared__ float tile[FJ][32][HT + 1];

    int blk   = blockIdx.x;          // htile*2 + half
    int half  = blk & 1;
    int htile = blk >> 1;
    int w = threadIdx.x >> 5;
    int p = threadIdx.x & 31;
    int h = htile * HT + w;

    const float4* AB4 = reinterpret_cast<const float4*>(g_AB4) + h * FNP;
    const float4* ab4 = reinterpret_cast<const float4*>(g_ab4) + h * FNP;
    const float4* wk4 = reinterpret_cast<const float4*>(g_wk4) + h * FNP;
    const float4* m4  = reinterpret_cast<const float4*>(g_m4)  + h * FNP;
    const float4* q4  = reinterpret_cast<const float4*>(g_q4)  + h * FNP;

    float lm = (float)(p - 32);

    u64 acc[FJ];
#pragma unroll
    for (int j = 0; j < FJ; j++) acc[j] = 0ULL;

    // prefetch np = 0
    float4 nab = __ldg(ab4);
    float4 nwk = __ldg(wk4);
    float4 nm  = __ldg(m4);
    float4 nAB = __ldg(AB4);
    float4 nq  = __ldg(q4);

    for (int np = 0; np < FNP; np++) {
        float4 cab = nab, cwk = nwk, cm4 = nm, cAB = nAB, cq = nq;
        if (np + 1 < FNP) {
            nab = __ldg(ab4 + np + 1);
            nwk = __ldg(wk4 + np + 1);
            nm  = __ldg(m4  + np + 1);
            nAB = __ldg(AB4 + np + 1);
            nq  = __ldg(q4  + np + 1);
        }

        // seeds: E = exp(dtL*(p-32)) per n, G = Wk*E (and *q for half 1)
        float e0 = __expf(cab.x * lm);
        float e1 = __expf(cab.y * lm);
        float s0, c0s, s1, c1s;
        fast_sincos(cab.z * lm, &s0, &c0s);
        fast_sincos(cab.w * lm, &s1, &c1s);
        float Er0 = e0 * c0s, Ei0 = e0 * s0;
        float Er1 = e1 * c1s, Ei1 = e1 * s1;

        float Gr0 = cwk.x * Er0 - cwk.z * Ei0;
        float Gi0 = cwk.x * Ei0 + cwk.z * Er0;
        float Gr1 = cwk.y * Er1 - cwk.w * Ei1;
        float Gi1 = cwk.y * Ei1 + cwk.w * Er1;

        if (half) {   // rotate by z^1024 (uniform branch per block)
            float tr0 = Gr0 * cq.x - Gi0 * cq.z;
            float ti0 = Gr0 * cq.z + Gi0 * cq.x;
            Gr0 = tr0; Gi0 = ti0;
            float tr1 = Gr1 * cq.y - Gi1 * cq.w;
            float ti1 = Gr1 * cq.w + Gi1 * cq.y;
            Gr1 = tr1; Gi1 = ti1;
        }

        // cm1 = Re(G)  (l = l0+p-32);  c0 = Re(G * z^32)  (l = l0+p)
        float c00 = Gr0 * cm4.x - Gi0 * cm4.z;
        float c01 = Gr1 * cm4.y - Gi1 * cm4.w;

        u64 c, cm, A, nB;
        PK(cm, Gr0, Gr1);
        PK(c,  c00, c01);
        PK(A,  cAB.x, cAB.y);
        PK(nB, cAB.z, cAB.w);

#pragma unroll
        for (int j = 0; j < FJ; j++) {
            ADD2(acc[j], acc[j], c);
            u64 t;
            MUL2(t, c, A);
            FMA2(t, cm, nB, t);
            cm = c;
            c = t;
        }
    }

    // stage: tile[j][p][w] = hsum(acc[j])
#pragma unroll
    for (int j = 0; j < FJ; j++) {
        float lo, hi;
        UPK(lo, hi, acc[j]);
        tile[j][p][w] = lo + hi;
    }
    __syncthreads();

    // coalesced store: out[l0 + 32k + pp, h0 + ww]
    int pp = threadIdx.x >> 3;
    int ww = threadIdx.x & 7;
    int l0 = half << 10;
    int hb = htile * HT + ww;
#pragma unroll
    for (int k = 0; k < FJ; k++)
        out[(size_t)(l0 + (k << 5) + pp) * FH + hb] = tile[k][pp][ww];
}

// ---------------------------------------------------------------------------
// Generic fallback (correct for any shape; slow).
// ---------------------------------------------------------------------------
__global__ void k_generic(const float* __restrict__ log_dt,
                          const float* __restrict__ llnr,
                          const float* __restrict__ lim,
                          const float* __restrict__ W,
                          float* __restrict__ out,
                          int H, int N, int L)
{
    int idx = blockIdx.x * blockDim.x + threadIdx.x;
    if (idx >= L * H) return;
    int l = idx / H, h = idx - l * H;
    float dtr = expf(log_dt[2 * h + 0]);
    float dti = expf(log_dt[2 * h + 1]);
    float fl = (float)l;
    float sum = 0.0f;
    for (int n = 0; n < N; n++) {
        float lr = -expf(llnr[n]);
        float li = lim[n];
        float a = dtr * lr, b = dti * li;
        float ns = fmaxf(lr * lr + li * li, EPS2);
        float rr = lr / ns, ri = -li / ns;
        float ea = expf(a), sb, cb;
        sincosf(b, &sb, &cb);
        float edr = ea * cb - 1.0f, edi = ea * sb;
        float wr = W[(h * N + n) * 2 + 0], wi = W[(h * N + n) * 2 + 1];
        float tr = wr * edr - wi * edi, ti = wr * edi + wi * edr;
        float wkr = tr * rr - ti * ri, wki = tr * ri + ti * rr;
        float el = expf(a * fl), sl, cl;
        sincosf(b * fl, &sl, &cl);
        sum += wkr * (el * cl) - wki * (el * sl);
    }
    out[idx] = sum;
}

// ---------------------------------------------------------------------------
extern "C" void kernel_launch(void* const* d_in, const int* in_sizes, int n_in,
                              void* d_out, int out_size)
{
    const float* log_dt = (const float*)d_in[0];   // (H,2)
    const float* llnr   = (const float*)d_in[1];   // (N,)
    const float* lim    = (const float*)d_in[2];   // (N,)
    const float* W      = (const float*)d_in[3];   // (H,N,2)
    float* out = (float*)d_out;

    int H = in_sizes[0] / 2;
    int N = in_sizes[1];
    int L = out_size / H;

    if (H == FH && N == FN && L == FL) {
        k_prep<<<(FH * FN + 255) / 256, 256>>>(log_dt, llnr, lim, W);
        k_main<<<(FH / HT) * 2, HT * 32>>>(out);
    } else {
        int tot = L * H;
        k_generic<<<(tot + 255) / 256, 256>>>(log_dt, llnr, lim, W, out, H, N, L);
    }
}

// round 5
// speedup vs baseline: 1.6070x; 1.0525x over previous
#include <cuda_runtime.h>
#include <cstdint>

// ---------------------------------------------------------------------------
// DSS kernel: out[l,h] = Re( sum_n Wk[h,n] * exp(dtLambda[h,n] * l) )
// Fastpath (H=1024, N=64, L=2048): SINGLE fused kernel.
//   Phase 1: block computes per-(h, n-pair) constants into smem (64 threads,
//            one n-pair each; DP Cody-Waite reduction for big angles).
//   Phase 2: per warp (one h), per n-pair: fast-trig seeds, then TWO
//            independent stride-64 real recurrences x+ = A2 x - B2 x-
//            in packed f32x2 (ILP 2 -> one warp saturates the fma pipe).
//   Phase 3: smem transpose, float2 coalesced stores to out[l, h].
// ---------------------------------------------------------------------------

#define EPS2 1e-14f   // EPS^2, EPS = 1e-7

#define FH 1024
#define FN 64
#define FL 2048
#define FNP 32          // n-pairs
#define HT  2           // h per block
#define NJJ 16          // recurrence steps (each covers 2 output phases)

#define INV_2PI 0.15915494309189535f
#define PI2_HI  6.2831854820251465f
#define PI2_LO  (-1.7484556000744483e-7f)
#define INV2PI_D 0.15915494309189535
#define TWOPI_D  6.283185307179586

typedef unsigned long long u64;
#define PK(d, lo, hi)   asm("mov.b64 %0, {%1, %2};" : "=l"(d) : "f"(lo), "f"(hi))
#define UPK(lo, hi, v)  asm("mov.b64 {%0, %1}, %2;" : "=f"(lo), "=f"(hi) : "l"(v))
#define MUL2(d, a, b)   asm("mul.rn.f32x2 %0, %1, %2;" : "=l"(d) : "l"(a), "l"(b))
#define ADD2(d, a, b)   asm("add.rn.f32x2 %0, %1, %2;" : "=l"(d) : "l"(a), "l"(b))
#define FMA2(d, a, b, c) asm("fma.rn.f32x2 %0, %1, %2, %3;" : "=l"(d) : "l"(a), "l"(b), "l"(c))

// fast sin/cos with explicit Cody-Waite reduction to [-pi, pi]
__device__ __forceinline__ void fast_sincos(float th, float* s, float* c)
{
    float k = rintf(th * INV_2PI);
    float r = fmaf(-k, PI2_HI, th);
    r = fmaf(-k, PI2_LO, r);
    *s = __sinf(r);
    *c = __cosf(r);
}

// precise small-angle for large multiples: reduce in double, sincosf on result
__device__ __forceinline__ void dp_sincos(float b, float mult, float* s, float* c)
{
    double th = (double)mult * (double)b;
    double k = rint(th * INV2PI_D);
    float r = (float)(th - k * TWOPI_D);
    sincosf(r, s, c);
}

// ---------------------------------------------------------------------------
// Fused kernel. Block = (htile, half): 64 threads, 2 warps.
//   blk = htile*2 + half ; h0 = htile*2 ; warp w handles h = h0 + w.
// smem const slots per (h_local, np), slot-major for conflict-free STS and
// broadcast LDS:
//   0: (a0, a1, b0, b1)
//   1: (wkr0, wkr1, -wki0, -wki1)
//   2: (wki0, wki1, qi0, qi1)
//   3: (m1r0, m1r1, -m1i0, -m1i1)      m1 = z^32
//   4: (m2r0, m2r1, -m2i0, -m2i1)      m2 = z^64
//   5: (m3r0, m3r1, -m3i0, -m3i1)      m3 = z^96
//   6: (qr0, qr1, -qi0, -qi1)          q  = z^1024
//   7: (A2_0, A2_1, -B2_0, -B2_1)
// ---------------------------------------------------------------------------
__global__ void __launch_bounds__(64, 7) k_fused(
    const float* __restrict__ log_dt,
    const float* __restrict__ llnr,
    const float* __restrict__ lim,
    const float* __restrict__ W,
    float* __restrict__ out)
{
    __shared__ float4 npcs[8][HT][FNP];
    __shared__ float tileA[32][33];
    __shared__ float tileB[32][33];

    const int blk   = blockIdx.x;
    const int half  = blk & 1;
    const int htile = blk >> 1;
    const int h0    = htile * HT;
    const int tid   = threadIdx.x;
    const int w     = tid >> 5;      // warp -> h_local
    const int p     = tid & 31;      // lane

    // ---------------- Phase 1: constants for (h0 + w', np') -----------------
    {
        const int hl = tid >> 5;
        const int np = tid & 31;
        const int h  = h0 + hl;

        float dtr = expf(log_dt[2 * h + 0]);
        float dti = expf(log_dt[2 * h + 1]);

        float a_[2], b_[2], wkr_[2], wki_[2];
        float m1r_[2], m1i_[2], m2r_[2], m2i_[2], m3r_[2], m3i_[2];
        float qr_[2], qi_[2], A2_[2], nB2_[2];

#pragma unroll
        for (int par = 0; par < 2; par++) {
            int n = 2 * np + par;
            float lr = -expf(llnr[n]);
            float li = lim[n];
            float a = dtr * lr;      // < 0
            float b = dti * li;
            a_[par] = a;  b_[par] = b;

            // Wk = Wc * (exp(dtL)-1) * reciprocal_clamped(Lambda)
            float ns = fmaxf(lr * lr + li * li, EPS2);
            float rr =  lr / ns;
            float ri = -li / ns;
            float ea = expf(a), sb, cb;
            sincosf(b, &sb, &cb);
            float edr = ea * cb - 1.0f;
            float edi = ea * sb;
            float wr = W[(h * FN + n) * 2 + 0];
            float wi = W[(h * FN + n) * 2 + 1];
            float tr = wr * edr - wi * edi;
            float ti = wr * edi + wi * edr;
            wkr_[par] = tr * rr - ti * ri;
            wki_[par] = tr * ri + ti * rr;

            // m1 = z^32 (DP-reduced angle)
            float s32, c32;
            dp_sincos(b, 32.0f, &s32, &c32);
            float e32 = expf(32.0f * a);
            float m1r = e32 * c32, m1i = e32 * s32;
            m1r_[par] = m1r;  m1i_[par] = m1i;
            // m2 = m1^2, m3 = m2*m1
            float m2r = m1r * m1r - m1i * m1i;
            float m2i = 2.0f * m1r * m1i;
            m2r_[par] = m2r;  m2i_[par] = m2i;
            m3r_[par] = m2r * m1r - m2i * m1i;
            m3i_[par] = m2r * m1i + m2i * m1r;

            // q = z^1024 (DP-reduced angle)
            float s1k, c1k;
            dp_sincos(b, 1024.0f, &s1k, &c1k);
            float e1k = expf(1024.0f * a);
            qr_[par] = e1k * c1k;
            qi_[par] = e1k * s1k;

            A2_[par]  = 2.0f * m2r;
            nB2_[par] = -expf(128.0f * a);
        }

        npcs[0][hl][np] = make_float4(a_[0], a_[1], b_[0], b_[1]);
        npcs[1][hl][np] = make_float4(wkr_[0], wkr_[1], -wki_[0], -wki_[1]);
        npcs[2][hl][np] = make_float4(wki_[0], wki_[1], qi_[0], qi_[1]);
        npcs[3][hl][np] = make_float4(m1r_[0], m1r_[1], -m1i_[0], -m1i_[1]);
        npcs[4][hl][np] = make_float4(m2r_[0], m2r_[1], -m2i_[0], -m2i_[1]);
        npcs[5][hl][np] = make_float4(m3r_[0], m3r_[1], -m3i_[0], -m3i_[1]);
        npcs[6][hl][np] = make_float4(qr_[0], qr_[1], -qi_[0], -qi_[1]);
        npcs[7][hl][np] = make_float4(A2_[0], A2_[1], -nB2_[0] * 0.0f - (-nB2_[0]) * 0.0f + nB2_[0], nB2_[1]);
    }
    __syncthreads();

    // ---------------- Phase 2: seeds + ILP-2 recurrence ---------------------
    const float lm = (float)p - 64.0f;     // G corresponds to l = half*1024 + p - 64

    u64 acc[32];
#pragma unroll
    for (int j = 0; j < 32; j++) acc[j] = 0ULL;

    for (int np = 0; np < FNP; np++) {
        float4 ab = npcs[0][w][np];
        ulonglong2 wkA = *reinterpret_cast<const ulonglong2*>(&npcs[1][w][np]); // .x=wkr2 .y=nwki2
        ulonglong2 wkB = *reinterpret_cast<const ulonglong2*>(&npcs[2][w][np]); // .x=wki2 .y=qi2
        ulonglong2 M1  = *reinterpret_cast<const ulonglong2*>(&npcs[3][w][np]);
        ulonglong2 M2  = *reinterpret_cast<const ulonglong2*>(&npcs[4][w][np]);
        ulonglong2 M3  = *reinterpret_cast<const ulonglong2*>(&npcs[5][w][np]);
        ulonglong2 Q   = *reinterpret_cast<const ulonglong2*>(&npcs[6][w][np]); // .x=qr2 .y=nqi2
        ulonglong2 AB  = *reinterpret_cast<const ulonglong2*>(&npcs[7][w][np]); // .x=A2  .y=-B2

        // E = exp(dtL * lm) per n (fast trig; a*lm in [0, ~3.3] so e in [1,~27])
        float e0 = __expf(ab.x * lm);
        float e1 = __expf(ab.y * lm);
        float s0, c0, s1, c1;
        fast_sincos(ab.z * lm, &s0, &c0);
        fast_sincos(ab.w * lm, &s1, &c1);
        float er0 = e0 * c0, ei0 = e0 * s0;
        float er1 = e1 * c1, ei1 = e1 * s1;
        u64 Er2, Ei2;
        PK(Er2, er0, er1);
        PK(Ei2, ei0, ei1);

        // G = Wk * E
        u64 Gr, Gi, t0, t1;
        MUL2(t0, wkA.x, Er2);  FMA2(Gr, wkA.y, Ei2, t0);   // wkr*Er - wki*Ei
        MUL2(t1, wkA.x, Ei2);  FMA2(Gi, wkB.x, Er2, t1);   // wkr*Ei + wki*Er
        if (half) {                                        // G *= z^1024
            u64 nr, ni;
            MUL2(nr, Gr, Q.x);  FMA2(nr, Q.y,   Gi, nr);   // Gr*qr - Gi*qi
            MUL2(ni, Gi, Q.x);  FMA2(ni, wkB.y, Gr, ni);   // Gi*qr + Gr*qi
            Gr = nr;  Gi = ni;
        }

        // seeds: even chain l = lb+p+64jj ; odd chain l = lb+p+32+64jj
        u64 cme = Gr;                                      // Re(G)         l = lb+p-64
        u64 ce, cmo, co;
        MUL2(ce,  Gr, M2.x);  FMA2(ce,  M2.y, Gi, ce);     // Re(G*z^64)    l = lb+p
        MUL2(cmo, Gr, M1.x);  FMA2(cmo, M1.y, Gi, cmo);    // Re(G*z^32)    l = lb+p-32
        MUL2(co,  Gr, M3.x);  FMA2(co,  M3.y, Gi, co);     // Re(G*z^96)    l = lb+p+32

        u64 A2 = AB.x, nB2 = AB.y;
#pragma unroll
        for (int jj = 0; jj < NJJ; jj++) {
            ADD2(acc[2 * jj],     acc[2 * jj],     ce);
            ADD2(acc[2 * jj + 1], acc[2 * jj + 1], co);
            u64 te, to;
            MUL2(te, ce, A2);  FMA2(te, cme, nB2, te);
            MUL2(to, co, A2);  FMA2(to, cmo, nB2, to);
            cme = ce;  ce = te;
            cmo = co;  co = to;
        }
    }

    // ---------------- Phase 3: transpose + coalesced stores -----------------
    {
        float (*tile)[33] = w ? tileB : tileA;
#pragma unroll
        for (int j = 0; j < 32; j++) {
            float lo, hi;
            UPK(lo, hi, acc[j]);
            tile[j][p] = lo + hi;
        }
    }
    __syncthreads();

    {
        const int kk = tid >> 5;        // 0 or 1 (k parity)
        const int pp = tid & 31;        // l phase within 32
        const int l0 = half << 10;
#pragma unroll
        for (int k = kk; k < 32; k += 2) {
            float2 v = make_float2(tileA[k][pp], tileB[k][pp]);
            *reinterpret_cast<float2*>(out + (size_t)(l0 + (k << 5) + pp) * FH + h0) = v;
        }
    }
}

// ---------------------------------------------------------------------------
// Generic fallback (correct for any shape; slow).
// ---------------------------------------------------------------------------
__global__ void k_generic(const float* __restrict__ log_dt,
                          const float* __restrict__ llnr,
                          const float* __restrict__ lim,
                          const float* __restrict__ W,
                          float* __restrict__ out,
                          int H, int N, int L)
{
    int idx = blockIdx.x * blockDim.x + threadIdx.x;
    if (idx >= L * H) return;
    int l = idx / H, h = idx - l * H;
    float dtr = expf(log_dt[2 * h + 0]);
    float dti = expf(log_dt[2 * h + 1]);
    float fl = (float)l;
    float sum = 0.0f;
    for (int n = 0; n < N; n++) {
        float lr = -expf(llnr[n]);
        float li = lim[n];
        float a = dtr * lr, b = dti * li;
        float ns = fmaxf(lr * lr + li * li, EPS2);
        float rr = lr / ns, ri = -li / ns;
        float ea = expf(a), sb, cb;
        sincosf(b, &sb, &cb);
        float edr = ea * cb - 1.0f, edi = ea * sb;
        float wr = W[(h * N + n) * 2 + 0], wi = W[(h * N + n) * 2 + 1];
        float tr = wr * edr - wi * edi, ti = wr * edi + wi * edr;
        float wkr = tr * rr - ti * ri, wki = tr * ri + ti * rr;
        float el = expf(a * fl), sl, cl;
        sincosf(b * fl, &sl, &cl);
        sum += wkr * (el * cl) - wki * (el * sl);
    }
    out[idx] = sum;
}

// ---------------------------------------------------------------------------
extern "C" void kernel_launch(void* const* d_in, const int* in_sizes, int n_in,
                              void* d_out, int out_size)
{
    const float* log_dt = (const float*)d_in[0];   // (H,2)
    const float* llnr   = (const float*)d_in[1];   // (N,)
    const float* lim    = (const float*)d_in[2];   // (N,)
    const float* W      = (const float*)d_in[3];   // (H,N,2)
    float* out = (float*)d_out;

    int H = in_sizes[0] / 2;
    int N = in_sizes[1];
    int L = out_size / H;

    if (H == FH && N == FN && L == FL) {
        k_fused<<<(FH / HT) * 2, HT * 32>>>(log_dt, llnr, lim, W, out);
    } else {
        int tot = L * H;
        k_generic<<<(tot + 255) / 256, 256>>>(log_dt, llnr, lim, W, out, H, N, L);
    }
}

// round 6
// speedup vs baseline: 1.6886x; 1.0508x over previous
#include <cuda_runtime.h>
#include <cstdint>

// ---------------------------------------------------------------------------
// DSS kernel: out[l,h] = Re( sum_n Wk[h,n] * exp(dtLambda[h,n] * l) )
// Fastpath (H=1024, N=64, L=2048): SINGLE fused kernel, software-pipelined.
//   Phase 1: block computes per-(h, n-pair) constants into smem; the z^1024
//            half-rotation is folded into Wk here (block knows its half).
//   Phase 2: per warp (one h): per n-pair fast-trig seeds (pipelined one np
//            ahead), then TWO independent stride-64 real recurrences
//            x+ = A2 x - B2 x- in packed f32x2.
//   Phase 3: smem transpose, float2 coalesced stores to out[l, h].
// ---------------------------------------------------------------------------

#define EPS2 1e-14f   // EPS^2, EPS = 1e-7

#define FH 1024
#define FN 64
#define FL 2048
#define FNP 32          // n-pairs
#define HT  2           // h per block
#define NJJ 16          // recurrence steps (each covers 2 output phases)

#define INV_2PI 0.15915494309189535f
#define PI2_HI  6.2831854820251465f
#define PI2_LO  (-1.7484556000744483e-7f)
#define INV2PI_D 0.15915494309189535
#define TWOPI_D  6.283185307179586

typedef unsigned long long u64;
#define PK(d, lo, hi)   asm("mov.b64 %0, {%1, %2};" : "=l"(d) : "f"(lo), "f"(hi))
#define UPK(lo, hi, v)  asm("mov.b64 {%0, %1}, %2;" : "=f"(lo), "=f"(hi) : "l"(v))
#define MUL2(d, a, b)   asm("mul.rn.f32x2 %0, %1, %2;" : "=l"(d) : "l"(a), "l"(b))
#define ADD2(d, a, b)   asm("add.rn.f32x2 %0, %1, %2;" : "=l"(d) : "l"(a), "l"(b))
#define FMA2(d, a, b, c) asm("fma.rn.f32x2 %0, %1, %2, %3;" : "=l"(d) : "l"(a), "l"(b), "l"(c))

// fast sin/cos with explicit Cody-Waite reduction to [-pi, pi]
__device__ __forceinline__ void fast_sincos(float th, float* s, float* c)
{
    float k = rintf(th * INV_2PI);
    float r = fmaf(-k, PI2_HI, th);
    r = fmaf(-k, PI2_LO, r);
    *s = __sinf(r);
    *c = __cosf(r);
}

// precise: reduce mult*b in double, then sincosf on the small residue
__device__ __forceinline__ void dp_sincos(float b, float mult, float* s, float* c)
{
    double th = (double)mult * (double)b;
    double k = rint(th * INV2PI_D);
    float r = (float)(th - k * TWOPI_D);
    sincosf(r, s, c);
}

// ---------------------------------------------------------------------------
// Fused kernel. Block = (htile, half): 64 threads, 2 warps, warp w -> h0+w.
// smem const slots per (h_local, np), each float4 (parity-packed pairs):
//   s0: (a0, a1, b0, b1)
//   s1: (wkr0, wkr1, nwki0, nwki1)       wk includes z^1024 rotation if half
//   s2: (wki0, wki1, m1r0, m1r1)         m1 = z^32
//   s3: (nm1i0, nm1i1, A1_0, A1_1)       A1 = 2 Re z^32
//   s4: (nB1_0, nB1_1, A2_0, A2_1)       B1 = e^{64a}, A2 = 2 Re z^64
//   s5: (nB2_0, nB2_1, 0, 0)             B2 = e^{128a}
// ---------------------------------------------------------------------------
__global__ void __launch_bounds__(64, 7) k_fused(
    const float* __restrict__ log_dt,
    const float* __restrict__ llnr,
    const float* __restrict__ lim,
    const float* __restrict__ W,
    float* __restrict__ out)
{
    __shared__ float4 npcs[6][HT][FNP];
    __shared__ float tileA[32][33];
    __shared__ float tileB[32][33];

    const int blk   = blockIdx.x;
    const int half  = blk & 1;
    const int htile = blk >> 1;
    const int h0    = htile * HT;
    const int tid   = threadIdx.x;
    const int w     = tid >> 5;
    const int p     = tid & 31;

    // ---------------- Phase 1: per-(h, np) constants -------------------------
    {
        const int hl = tid >> 5;
        const int np = tid & 31;
        const int h  = h0 + hl;

        float dtr = expf(log_dt[2 * h + 0]);
        float dti = expf(log_dt[2 * h + 1]);

        float a_[2], b_[2], wkr_[2], wki_[2];
        float m1r_[2], nm1i_[2], A1_[2], nB1_[2], A2_[2], nB2_[2];

#pragma unroll
        for (int par = 0; par < 2; par++) {
            int n = 2 * np + par;
            float lr = -expf(llnr[n]);
            float li = lim[n];
            float a = dtr * lr;      // < 0
            float b = dti * li;
            a_[par] = a;  b_[par] = b;

            // Wk = Wc * (exp(dtL)-1) * reciprocal_clamped(Lambda)
            float ns = fmaxf(lr * lr + li * li, EPS2);
            float rr =  lr / ns;
            float ri = -li / ns;
            float ea = expf(a), sb, cb;
            sincosf(b, &sb, &cb);
            float edr = ea * cb - 1.0f;
            float edi = ea * sb;
            float wr = W[(h * FN + n) * 2 + 0];
            float wi = W[(h * FN + n) * 2 + 1];
            float tr = wr * edr - wi * edi;
            float ti = wr * edi + wi * edr;
            float wkr = tr * rr - ti * ri;
            float wki = tr * ri + ti * rr;

            if (half) {              // fold z^1024 rotation into Wk (precise)
                float s1k, c1k;
                dp_sincos(b, 1024.0f, &s1k, &c1k);
                float e1k = expf(1024.0f * a);
                float qr = e1k * c1k, qi = e1k * s1k;
                float nwr = wkr * qr - wki * qi;
                float nwi = wkr * qi + wki * qr;
                wkr = nwr;  wki = nwi;
            }
            wkr_[par] = wkr;  wki_[par] = wki;

            // m1 = z^32 (DP-reduced angle)
            float s32, c32;
            dp_sincos(b, 32.0f, &s32, &c32);
            float e32 = expf(32.0f * a);
            float m1r = e32 * c32, m1i = e32 * s32;
            m1r_[par]  = m1r;
            nm1i_[par] = -m1i;

            float e64 = e32 * e32;                // e^{64a}
            A1_[par]  = 2.0f * m1r;
            nB1_[par] = -e64;
            A2_[par]  = 2.0f * (m1r * m1r - m1i * m1i);
            nB2_[par] = -e64 * e64;               // -e^{128a}
        }

        npcs[0][hl][np] = make_float4(a_[0], a_[1], b_[0], b_[1]);
        npcs[1][hl][np] = make_float4(wkr_[0], wkr_[1], -wki_[0], -wki_[1]);
        npcs[2][hl][np] = make_float4(wki_[0], wki_[1], m1r_[0], m1r_[1]);
        npcs[3][hl][np] = make_float4(nm1i_[0], nm1i_[1], A1_[0], A1_[1]);
        npcs[4][hl][np] = make_float4(nB1_[0], nB1_[1], A2_[0], A2_[1]);
        npcs[5][hl][np] = make_float4(nB2_[0], nB2_[1], 0.0f, 0.0f);
    }
    __syncthreads();

    // ---------------- Phase 2: pipelined seeds + ILP-2 recurrence ------------
    const float lm = (float)p - 64.0f;   // seed G sits at l = half*1024 + p - 64

    u64 acc[32];
#pragma unroll
    for (int j = 0; j < 32; j++) acc[j] = 0ULL;

    // seed computation for one np -> chain state (cme, cmo, ce, co, A2, nB2)
    auto seeds = [&](int np, u64& cme, u64& cmo, u64& ce, u64& co,
                     u64& A2, u64& nB2) {
        float4 ab = npcs[0][w][np];
        ulonglong2 s1 = *reinterpret_cast<const ulonglong2*>(&npcs[1][w][np]);
        ulonglong2 s2 = *reinterpret_cast<const ulonglong2*>(&npcs[2][w][np]);
        ulonglong2 s3 = *reinterpret_cast<const ulonglong2*>(&npcs[3][w][np]);
        ulonglong2 s4 = *reinterpret_cast<const ulonglong2*>(&npcs[4][w][np]);
        ulonglong2 s5 = *reinterpret_cast<const ulonglong2*>(&npcs[5][w][np]);
        // s1.x=wkr2 s1.y=nwki2 ; s2.x=wki2 s2.y=m1r2 ; s3.x=nm1i2 s3.y=A1_2
        // s4.x=nB1_2 s4.y=A2_2 ; s5.x=nB2_2

        float e0 = __expf(ab.x * lm);
        float e1 = __expf(ab.y * lm);
        float s0f, c0f, s1f, c1f;
        fast_sincos(ab.z * lm, &s0f, &c0f);
        fast_sincos(ab.w * lm, &s1f, &c1f);
        u64 Er2, Ei2;
        PK(Er2, e0 * c0f, e1 * c1f);
        PK(Ei2, e0 * s0f, e1 * s1f);

        u64 Gr, Gi, t;
        MUL2(t, s1.x, Er2);  FMA2(Gr, s1.y, Ei2, t);    // wkr*Er - wki*Ei
        MUL2(t, s1.x, Ei2);  FMA2(Gi, s2.x, Er2, t);    // wkr*Ei + wki*Er

        cme = Gr;                                        // x(p-64)
        MUL2(t, s2.y, Gr);   FMA2(cmo, s3.x, Gi, t);     // Re(G*z^32) x(p-32)
        MUL2(t, s3.y, cmo);  FMA2(ce,  s4.x, cme, t);    // x(p)
        MUL2(t, s3.y, ce);   FMA2(co,  s4.x, cmo, t);    // x(p+32)
        A2  = s4.y;
        nB2 = s5.x;
    };

    // recurrence body for one np (chain state passed in)
    auto body = [&](u64 cme, u64 cmo, u64 ce, u64 co, u64 A2, u64 nB2) {
#pragma unroll
        for (int jj = 0; jj < NJJ; jj++) {
            ADD2(acc[2 * jj],     acc[2 * jj],     ce);
            ADD2(acc[2 * jj + 1], acc[2 * jj + 1], co);
            u64 te, to;
            MUL2(te, ce, A2);  FMA2(te, cme, nB2, te);
            MUL2(to, co, A2);  FMA2(to, cmo, nB2, to);
            cme = ce;  ce = te;
            cmo = co;  co = to;
        }
    };

    u64 cme, cmo, ce, co, A2, nB2;
    seeds(0, cme, cmo, ce, co, A2, nB2);

#pragma unroll 1
    for (int np = 0; np < FNP - 1; np++) {
        u64 ncme, ncmo, nce, nco, nA2, nnB2;
        seeds(np + 1, ncme, ncmo, nce, nco, nA2, nnB2);  // hidden under body
        body(cme, cmo, ce, co, A2, nB2);
        cme = ncme;  cmo = ncmo;  ce = nce;  co = nco;
        A2 = nA2;  nB2 = nnB2;
    }
    body(cme, cmo, ce, co, A2, nB2);                     // epilogue np = 31

    // ---------------- Phase 3: transpose + coalesced stores ------------------
    {
        float (*tile)[33] = w ? tileB : tileA;
#pragma unroll
        for (int j = 0; j < 32; j++) {
            float lo, hi;
            UPK(lo, hi, acc[j]);
            tile[j][p] = lo + hi;
        }
    }
    __syncthreads();

    {
        const int kk = tid >> 5;
        const int pp = tid & 31;
        const int l0 = half << 10;
#pragma unroll
        for (int k = kk; k < 32; k += 2) {
            float2 v = make_float2(tileA[k][pp], tileB[k][pp]);
            *reinterpret_cast<float2*>(out + (size_t)(l0 + (k << 5) + pp) * FH + h0) = v;
        }
    }
}

// ---------------------------------------------------------------------------
// Generic fallback (correct for any shape; slow).
// ---------------------------------------------------------------------------
__global__ void k_generic(const float* __restrict__ log_dt,
                          const float* __restrict__ llnr,
                          const float* __restrict__ lim,
                          const float* __restrict__ W,
                          float* __restrict__ out,
                          int H, int N, int L)
{
    int idx = blockIdx.x * blockDim.x + threadIdx.x;
    if (idx >= L * H) return;
    int l = idx / H, h = idx - l * H;
    float dtr = expf(log_dt[2 * h + 0]);
    float dti = expf(log_dt[2 * h + 1]);
    float fl = (float)l;
    float sum = 0.0f;
    for (int n = 0; n < N; n++) {
        float lr = -expf(llnr[n]);
        float li = lim[n];
        float a = dtr * lr, b = dti * li;
        float ns = fmaxf(lr * lr + li * li, EPS2);
        float rr = lr / ns, ri = -li / ns;
        float ea = expf(a), sb, cb;
        sincosf(b, &sb, &cb);
        float edr = ea * cb - 1.0f, edi = ea * sb;
        float wr = W[(h * N + n) * 2 + 0], wi = W[(h * N + n) * 2 + 1];
        float tr = wr * edr - wi * edi, ti = wr * edi + wi * edr;
        float wkr = tr * rr - ti * ri, wki = tr * ri + ti * rr;
        float el = expf(a * fl), sl, cl;
        sincosf(b * fl, &sl, &cl);
        sum += wkr * (el * cl) - wki * (el * sl);
    }
    out[idx] = sum;
}

// ---------------------------------------------------------------------------
extern "C" void kernel_launch(void* const* d_in, const int* in_sizes, int n_in,
                              void* d_out, int out_size)
{
    const float* log_dt = (const float*)d_in[0];   // (H,2)
    const float* llnr   = (const float*)d_in[1];   // (N,)
    const float* lim    = (const float*)d_in[2];   // (N,)
    const float* W      = (const float*)d_in[3];   // (H,N,2)
    float* out = (float*)d_out;

    int H = in_sizes[0] / 2;
    int N = in_sizes[1];
    int L = out_size / H;

    if (H == FH && N == FN && L == FL) {
        k_fused<<<(FH / HT) * 2, HT * 32>>>(log_dt, llnr, lim, W, out);
    } else {
        int tot = L * H;
        k_generic<<<(tot + 255) / 256, 256>>>(log_dt, llnr, lim, W, out, H, N, L);
    }
}